// round 16
// baseline (speedup 1.0000x reference)
#include <cuda_runtime.h>
#include <cuda_bf16.h>

// x  : (1, 64, 28, 28) fp32 -> (2 groups o, 32 ch j, 28 n, 28 m)
// w1 : (128, 9),  w2 : (32, 7, 9)
// out: (1, 256, 28, 28), channel = o*128 + c, rolled +1 along height.
//
// t4[o,n,m,i]         = sum_{j,k} x[o*32+j, n, m+k-3] * w2[j,k,i]
// out[o,c,(n+1)%28,m] = sum_i w1[c,i] * t4[o,n,m,i]
//
// Grid 112 = (og, n, m-half), 288 threads. t4 warp = i, lane = (q, m-pair).
// NEW vs R15: x is loaded GMEM -> registers directly in each t4 thread
// (64 predicated __ldg, zero-fill halo). No xs smem, no staging loop, no
// first barrier, no LDS window. ONE __syncthreads in the whole kernel.

#define NTHREADS 288

__global__ __launch_bounds__(NTHREADS)
void fused_unfold_einsum_kernel(const float* __restrict__ x,
                                const float* __restrict__ w1,
                                const float* __restrict__ w2,
                                float* __restrict__ out) {
    __shared__ __align__(16) float t4s[14 * 12];   // [m_local][i], stride 12

    const int tid    = threadIdx.x;
    const int b      = blockIdx.x;      // 0..111
    const int og     = b / 56;
    const int r      = b - og * 56;
    const int n      = r >> 1;
    const int mh     = r & 1;
    const int m_base = mh * 14;

    const int i    = tid >> 5;          // warp id = i (0..8)
    const int lane = tid & 31;
    const int lq   = lane / 7;
    const int q    = lq & 3;            // lanes 28..31 -> q=0 (dup, discarded)
    const int mp   = lane - lq * 7;     // 0..6
    const int m0   = mp * 2;            // local m of first output

    // --- Prefetch this thread's 56 t4 weights to registers:
    //     wreg[jj][k] = w2[(row*7+k)*9 + i], row = q + 4*jj.
    float wreg[8][7];
    #pragma unroll
    for (int jj = 0; jj < 8; ++jj) {
        const int base = (q + 4 * jj) * 63 + i;     // (row*7+0)*9 + i
        #pragma unroll
        for (int k = 0; k < 7; ++k)
            wreg[jj][k] = __ldg(&w2[base + k * 9]);
    }

    // --- Prefetch this thread's w1 row to registers (phase 2).
    const int c    = tid & 127;
    const int mseg = (tid >> 7) & 1;
    float w1r[9];
    #pragma unroll
    for (int ii = 0; ii < 9; ++ii)
        w1r[ii] = __ldg(&w1[c * 9 + ii]);

    // --- Load this thread's x window straight to registers:
    //     xr[jj][pos] = x[og*32+row, n, mg],  mg = m_base + m0 - 3 + pos,
    //     zero outside [0,28). All 64 loads independent (MLP ~64).
    float xr[8][8];
    {
        const float* __restrict__ xb = x + og * 25088 + n * 28;  // + row*784 + mg
        #pragma unroll
        for (int pos = 0; pos < 8; ++pos) {
            const int mg = m_base + m0 - 3 + pos;
            const bool ok = (mg >= 0) && (mg < 28);
            #pragma unroll
            for (int jj = 0; jj < 8; ++jj) {
                const int row = q + 4 * jj;
                xr[jj][pos] = ok ? __ldg(xb + row * 784 + mg) : 0.0f;
            }
        }
    }

    // --- t4: 112 FMAs over 4 accumulators, all operands in registers.
    {
        float r0a = 0.f, r0b = 0.f, r1a = 0.f, r1b = 0.f;
        #pragma unroll
        for (int jj = 0; jj < 8; ++jj) {
            const float px0 = xr[jj][0], px1 = xr[jj][1];
            const float px2 = xr[jj][2], px3 = xr[jj][3];
            const float px4 = xr[jj][4], px5 = xr[jj][5];
            const float px6 = xr[jj][6], px7 = xr[jj][7];
            r0a = fmaf(px0, wreg[jj][0], r0a);  r1a = fmaf(px1, wreg[jj][0], r1a);
            r0a = fmaf(px1, wreg[jj][1], r0a);  r1a = fmaf(px2, wreg[jj][1], r1a);
            r0a = fmaf(px2, wreg[jj][2], r0a);  r1a = fmaf(px3, wreg[jj][2], r1a);
            r0a = fmaf(px3, wreg[jj][3], r0a);  r1a = fmaf(px4, wreg[jj][3], r1a);
            r0b = fmaf(px4, wreg[jj][4], r0b);  r1b = fmaf(px5, wreg[jj][4], r1b);
            r0b = fmaf(px5, wreg[jj][5], r0b);  r1b = fmaf(px6, wreg[jj][5], r1b);
            r0b = fmaf(px6, wreg[jj][6], r0b);  r1b = fmaf(px7, wreg[jj][6], r1b);
        }
        float r0 = r0a + r0b;
        float r1 = r1a + r1b;

        // Reduce the 4 quarters (lanes q*7+mp): +14 then +7.
        r0 += __shfl_down_sync(0xFFFFFFFFu, r0, 14);
        r1 += __shfl_down_sync(0xFFFFFFFFu, r1, 14);
        r0 += __shfl_down_sync(0xFFFFFFFFu, r0, 7);
        r1 += __shfl_down_sync(0xFFFFFFFFu, r1, 7);
        if (lane < 7) {                 // q==0 lanes hold the full sums
            t4s[(m0 + 0) * 12 + i] = r0;
            t4s[(m0 + 1) * 12 + i] = r1;
        }
    }
    __syncthreads();                    // the only barrier

    // --- Phase 2 (threads 0..255): c-major, w1 in regs, t4s via broadcast
    //     LDS.128, 2 m's per 8B-aligned STG.64.
    if (tid < 256) {
        const int nout   = (n + 1) % 28;    // jnp.roll(y, +1, axis=2)
        const int mstart = mseg ? 8 : 0;
        const int ngrp   = mseg ? 3 : 4;
        float* __restrict__ orow =
            &out[((og * 128 + c) * 28 + nout) * 28 + m_base];

        #pragma unroll
        for (int gp = 0; gp < 4; ++gp) {
            if (gp < ngrp) {                // warp-uniform predicate
                float o2[2];
                #pragma unroll
                for (int qq = 0; qq < 2; ++qq) {
                    const int m = mstart + gp * 2 + qq;
                    const float4* __restrict__ tv =
                        reinterpret_cast<const float4*>(&t4s[m * 12]);
                    const float4 v0 = tv[0], v1 = tv[1], v2 = tv[2];
                    float acc = v0.x * w1r[0];
                    acc = fmaf(v0.y, w1r[1], acc);
                    acc = fmaf(v0.z, w1r[2], acc);
                    acc = fmaf(v0.w, w1r[3], acc);
                    acc = fmaf(v1.x, w1r[4], acc);
                    acc = fmaf(v1.y, w1r[5], acc);
                    acc = fmaf(v1.z, w1r[6], acc);
                    acc = fmaf(v1.w, w1r[7], acc);
                    acc = fmaf(v2.x, w1r[8], acc);
                    o2[qq] = acc;
                }
                *reinterpret_cast<float2*>(&orow[mstart + gp * 2]) =
                    make_float2(o2[0], o2[1]);
            }
        }
    }
}

extern "C" void kernel_launch(void* const* d_in, const int* in_sizes, int n_in,
                              void* d_out, int out_size) {
    const float* x  = (const float*)d_in[0];
    const float* w1 = (const float*)d_in[1];
    const float* w2 = (const float*)d_in[2];
    float* out = (float*)d_out;
    (void)in_sizes; (void)n_in; (void)out_size;

    fused_unfold_einsum_kernel<<<112, NTHREADS>>>(x, w1, w2, out);
}